// round 13
// baseline (speedup 1.0000x reference)
#include <cuda_runtime.h>
#include <cuda_fp16.h>
#include <stdint.h>
#include <math.h>

#define BB 64
#define TT 512
#define II 256
#define HH 1024
#define OO 10
#define KTOT 1280
#define NCOL 4096
#define GRID 128
#define NT 256
#define NG 32              // batch rows per independent group

#define AROW 2560          // bytes per resident-A row (1280 k * 2B fp16)
#define OFF_B 81920        // B buffers after 80KB resident A
#define SLOT  4096         // one 64-k chunk for 32 rows (32*128B)
#define BUFSTRIDE 17408    // 4 slots (16KB) + headroom for 16.9KB scratch
#define DYN_SMEM (OFF_B + 3 * BUFSTRIDE)   // 134144

#define SW(o) ((o) ^ (((o) >> 3) & 0x70))

// ---------------- persistent device state ----------------
__device__ __half g_W[NCOL * KTOT];         // [col][k], col = cta*32 + g*8 + hloc
__device__ __half g_x[BB * TT * II];
__device__ __half g_h[2][2][NG * HH];       // [group][parity][b*HH+hj]
__device__ unsigned int g_cnt_grp[2][16];
__device__ unsigned int g_cnt_top[2];
__device__ volatile unsigned int g_gen2[2];

__device__ __forceinline__ uint32_t smem_u32(const void* p) {
    uint32_t a;
    asm("{ .reg .u64 t; cvta.to.shared.u64 t, %1; cvt.u32.u64 %0, t; }" : "=r"(a) : "l"(p));
    return a;
}

#define LDSM4(r, a) \
    asm volatile("ldmatrix.sync.aligned.m8n8.x4.shared.b16 {%0,%1,%2,%3}, [%4];" \
        : "=r"((r)[0]), "=r"((r)[1]), "=r"((r)[2]), "=r"((r)[3]) : "r"(a))

#define MMA(acc, a, b0, b1) \
    asm volatile("mma.sync.aligned.m16n8k16.row.col.f32.f16.f16.f32 " \
        "{%0,%1,%2,%3},{%4,%5,%6,%7},{%8,%9},{%0,%1,%2,%3};" \
        : "+f"((acc)[0]), "+f"((acc)[1]), "+f"((acc)[2]), "+f"((acc)[3]) \
        : "r"((a)[0]), "r"((a)[1]), "r"((a)[2]), "r"((a)[3]), "r"(b0), "r"(b1))

#define CP_ASYNC(dst, src) \
    asm volatile("cp.async.cg.shared.global [%0], [%1], 16;" :: "r"(dst), "l"(src))
#define CP_COMMIT() asm volatile("cp.async.commit_group;" ::: "memory")
#define CP_WAIT0()  asm volatile("cp.async.wait_group 0;" ::: "memory")
#define CP_WAIT1()  asm volatile("cp.async.wait_group 1;" ::: "memory")

__device__ __forceinline__ float fast_tanh(float x) {
    float e = __expf(2.0f * x);
    return 1.0f - 2.0f / (e + 1.0f);
}
__device__ __forceinline__ float fast_sig(float x) {
    return 1.0f / (1.0f + __expf(-x));
}

// ---------------- setup ----------------
__global__ void setup_kernel(const float* __restrict__ x,
                             const float* __restrict__ Wx,
                             const float* __restrict__ Wh)
{
    int gt = blockIdx.x * blockDim.x + threadIdx.x;
    int stride = gridDim.x * blockDim.x;

    for (int i = gt; i < NCOL * KTOT; i += stride) {
        int cf = i / KTOT, k = i - cf * KTOT;
        int cta = cf >> 5, r = cf & 31;
        int g = r >> 3, hj = cta * 8 + (r & 7);
        float w = (k < HH) ? Wh[(g * HH + k) * HH + hj]
                           : Wx[(g * II + (k - HH)) * HH + hj];
        g_W[i] = __float2half(w);
    }
    for (int i = gt; i < BB * TT * II; i += stride)
        g_x[i] = __float2half(x[i]);
    for (int i = gt; i < 2 * 2 * NG * HH; i += stride)
        ((__half*)g_h)[i] = __float2half(0.0f);
}

// ---------------- staging helpers ----------------
__device__ __forceinline__ void stage_h(const __half* hs, int c0,
                                        uint32_t bufbase, int tid) {
#pragma unroll
    for (int s = 0; s < 4; s++) {
        int gi = tid + s * NT;
        int slot = gi >> 8;
        int rem = gi & 255;
        int n = rem >> 3, kg = rem & 7;
        const __half* src = hs + n * HH + (c0 + slot) * 64 + kg * 8;
        uint32_t dst = bufbase + slot * SLOT + SW(n * 128 + kg * 16);
        CP_ASYNC(dst, src);
    }
}

__device__ __forceinline__ void stage_x(int grp, int tt, uint32_t bufbase, int tid) {
#pragma unroll
    for (int s = 0; s < 4; s++) {
        int gi = tid + s * NT;
        int slot = gi >> 8;
        int rem = gi & 255;
        int n = rem >> 3, kg = rem & 7;
        const __half* src = g_x + ((grp * NG + n) * TT + tt) * II + slot * 64 + kg * 8;
        uint32_t dst = bufbase + slot * SLOT + SW(n * 128 + kg * 16);
        CP_ASYNC(dst, src);
    }
}

__device__ __forceinline__ void compute_chunk(uint32_t slotB, int chunk,
                                              uint32_t aB0, uint32_t aB1,
                                              uint32_t bR0,
                                              int la, int lb, int lc,
                                              float acc[2][2][4]) {
#pragma unroll
    for (int ks = 0; ks < 4; ks++) {
        uint32_t ah0[4], ah1[4], bhf[4];
        uint32_t aoff = (uint32_t)(((chunk * 8 + ks * 2 + lc) ^ la) * 16);
        LDSM4(ah0, aB0 + aoff);
        LDSM4(ah1, aB1 + aoff);
        uint32_t boff = (uint32_t)(((ks * 2 + lb) ^ la) * 16);
        LDSM4(bhf, slotB + bR0 + boff);
        MMA(acc[0][0], ah0, bhf[0], bhf[1]);
        MMA(acc[0][1], ah0, bhf[2], bhf[3]);
        MMA(acc[1][0], ah1, bhf[0], bhf[1]);
        MMA(acc[1][1], ah1, bhf[2], bhf[3]);
    }
}

// ---------------- persistent HMMA LSTM: 2 interleaved batch groups ----------------
__global__ __launch_bounds__(NT, 1)
void lstm_mma_kernel(const float* __restrict__ bx,
                     const float* __restrict__ bh,
                     const float* __restrict__ Wp,
                     const float* __restrict__ bp,
                     float* __restrict__ out)
{
    extern __shared__ char smem[];
    const uint32_t sb = smem_u32(smem);
    const int tid = threadIdx.x;
    const int w   = tid >> 5;
    const int l   = tid & 31;
    const int cta = blockIdx.x;
    const int col0 = cta * 32;
    const int nh = w & 1;          // batch half within group: rows nh*16..+15
    const int kh = w >> 1;         // k-split quarter: 0..3

    const int la = l & 7, lb = (l >> 3) & 1, lc = l >> 4;

    const unsigned base0 = g_gen2[0];   // replay-safe bases
    const unsigned base1 = g_gen2[1];

    const uint32_t aB0 = sb + (uint32_t)((lb * 8 + la) * AROW);
    const uint32_t aB1 = aB0 + 16 * AROW;
    const uint32_t bR0 = (uint32_t)((nh * 16 + lc * 8 + la) * 128);

    // ---- one-time: load resident A (80KB fp16) ----
#pragma unroll 4
    for (int s = 0; s < 20; s++) {
        int idx = tid + s * NT;
        int r = idx / 160, kg = idx - r * 160;
        const __half* src = g_W + (col0 + r) * KTOT + kg * 8;
        uint32_t dst = sb + r * AROW + ((kg ^ (r & 7)) * 16);
        CP_ASYNC(dst, src);
    }
    CP_COMMIT(); CP_WAIT0();
    __syncthreads();

    // epilogue ownership: thread owns cell (b=l within group, hjE=cta*8+w)
    const int hjE = cta * 8 + w;
    const int nh2 = l >> 4;
    const int nf2 = (l >> 3) & 1;
    const int lsrc = w * 4 + ((l & 7) >> 1);
    const int par = l & 1;
    float biasE[4];
#pragma unroll
    for (int g = 0; g < 4; g++) biasE[g] = bh[g * HH + hjE] + bx[g * HH + hjE];
    float cc2[2] = {0.f, 0.f};     // c state per group

    // prologue: x(group0, t=0) into buffer 0
    stage_x(0, 0, sb + OFF_B, tid);
    CP_COMMIT();

    for (int ms = 0; ms < 2 * TT; ms++) {
        const int g = ms & 1, t = ms >> 1;
        const __half* hs = g_h[g][t & 1];
        const int bbi = (2 * ms) % 3;
        const uint32_t buf0 = sb + OFF_B + (uint32_t)(((bbi + 0) % 3) * BUFSTRIDE);
        const uint32_t buf1 = sb + OFF_B + (uint32_t)(((bbi + 1) % 3) * BUFSTRIDE);
        const uint32_t buf2 = sb + OFF_B + (uint32_t)(((bbi + 2) % 3) * BUFSTRIDE);

        float acc[2][2][4];
#pragma unroll
        for (int mt = 0; mt < 2; mt++)
#pragma unroll
            for (int nf = 0; nf < 2; nf++)
#pragma unroll
                for (int e = 0; e < 4; e++) acc[mt][nf][e] = 0.f;

        // ---- iter0: x chunks (16..19) — independent of h(g,t) ----
        CP_WAIT0();
        __syncthreads();
        compute_chunk(buf0 + kh * SLOT, 16 + kh, aB0, aB1, bR0, la, lb, lc, acc);

        // ---- group-g barrier wait (should be pre-satisfied: arrived 1 mini-step ago) ----
        {
            const unsigned baseg = g ? base1 : base0;
            while ((g_gen2[g] - baseg) < (unsigned)t) { }
        }
        __threadfence();

        stage_h(hs, 0, buf1, tid); CP_COMMIT();
        stage_h(hs, 4, buf2, tid); CP_COMMIT();

        // ---- iter1 ----
        CP_WAIT1();
        __syncthreads();
        stage_h(hs, 8, buf0, tid); CP_COMMIT();
        compute_chunk(buf1 + kh * SLOT, 0 + kh, aB0, aB1, bR0, la, lb, lc, acc);

        // ---- iter2 ----
        CP_WAIT1();
        __syncthreads();
        stage_h(hs, 12, buf1, tid); CP_COMMIT();
        compute_chunk(buf2 + kh * SLOT, 4 + kh, aB0, aB1, bR0, la, lb, lc, acc);

        // ---- iter3: prefetch next mini-step's x (other group) ----
        CP_WAIT1();
        __syncthreads();
        const bool more = (ms + 1 < 2 * TT);
        if (more) { stage_x(1 - g, t + g, buf2, tid); CP_COMMIT(); }
        compute_chunk(buf0 + kh * SLOT, 8 + kh, aB0, aB1, bR0, la, lb, lc, acc);

        // ---- iter4 ----
        if (more) { CP_WAIT1(); } else { CP_WAIT0(); }
        __syncthreads();
        compute_chunk(buf1 + kh * SLOT, 12 + kh, aB0, aB1, bR0, la, lb, lc, acc);

        // ---- all-warp reduction + epilogue (scratch in buf0: reads retired) ----
        float* scratch = (float*)(smem + (buf0 - sb));
        {
            float* dst = scratch + (kh * 2 + nh) * 528;
#pragma unroll
            for (int mt = 0; mt < 2; mt++)
#pragma unroll
                for (int nf = 0; nf < 2; nf++)
#pragma unroll
                    for (int e = 0; e < 4; e++)
                        dst[((mt * 2 + nf) * 4 + e) * 33 + l] = acc[mt][nf][e];
        }
        __syncthreads();

        {
            float zs[2][4];
#pragma unroll
            for (int mt = 0; mt < 2; mt++)
#pragma unroll
                for (int e = 0; e < 4; e++) {
                    int row = ((mt * 2 + nf2) * 4 + e) * 33 + lsrc;
                    float s0 = scratch[(0 + nh2) * 528 + row];
                    float s1 = scratch[(2 + nh2) * 528 + row];
                    float s2 = scratch[(4 + nh2) * 528 + row];
                    float s3 = scratch[(6 + nh2) * 528 + row];
                    zs[mt][e] = (s0 + s1) + (s2 + s3);
                }
            float zg = zs[0][par]     + biasE[0];
            float zi = zs[0][2 + par] + biasE[1];
            float zf = zs[1][par]     + biasE[2];
            float zo = zs[1][2 + par] + biasE[3];
            float gg = fast_tanh(zg);
            float ii = fast_sig(zi);
            float ff = fast_sig(zf);
            float oo = fast_sig(zo);
            float cv = gg * ii + cc2[g] * ff;
            cc2[g] = cv;
            float hv = fast_tanh(cv) * oo;
            g_h[g][(t + 1) & 1][l * HH + hjE] = __float2half(hv);
        }
        __syncthreads();   // h stores + scratch reads complete

        // ---- per-group two-level arrive ----
        if (tid == 0) {
            __threadfence();
            unsigned grp = (unsigned)cta >> 3;
            unsigned o1 = atomicAdd(&g_cnt_grp[g][grp], 1u);
            if ((o1 & 7u) == 7u) {
                unsigned o2 = atomicAdd(&g_cnt_top[g], 1u);
                if ((o2 & 15u) == 15u) {
                    __threadfence();
                    g_gen2[g] = (g ? base1 : base0) + (unsigned)(t + 1);
                }
            }
        }
    }

    // ---------- final projection + softmax ----------
    if (blockIdx.x < BB) {
        if (tid == 0) {
            while ((g_gen2[0] - base0) < (unsigned)TT) { }
            while ((g_gen2[1] - base1) < (unsigned)TT) { }
        }
        __syncthreads();
        __threadfence();

        float* red    = (float*)(smem + OFF_B);
        float* logits = red + NT;
        const int b = blockIdx.x;
        const int grp = b >> 5, br = b & 31;
        float part[OO];
#pragma unroll
        for (int o = 0; o < OO; o++) part[o] = 0.f;
        for (int k = tid; k < HH; k += NT) {
            unsigned short uh = __ldcg((const unsigned short*)&g_h[grp][0][br * HH + k]);
            float hv = __half2float(__ushort_as_half(uh));
#pragma unroll
            for (int o = 0; o < OO; o++) part[o] += hv * Wp[k * OO + o];
        }
        for (int o = 0; o < OO; o++) {
            red[tid] = part[o];
            __syncthreads();
            for (int s = NT / 2; s > 0; s >>= 1) {
                if (tid < s) red[tid] += red[tid + s];
                __syncthreads();
            }
            if (tid == 0) logits[o] = red[0] + bp[o];
            __syncthreads();
        }
        if (tid == 0) {
            float m = logits[0];
#pragma unroll
            for (int o = 1; o < OO; o++) m = fmaxf(m, logits[o]);
            float s = 0.f, e[OO];
#pragma unroll
            for (int o = 0; o < OO; o++) { e[o] = expf(logits[o] - m); s += e[o]; }
            float inv = 1.0f / s;
#pragma unroll
            for (int o = 0; o < OO; o++) out[b * OO + o] = e[o] * inv;
        }
    }
}

extern "C" void kernel_launch(void* const* d_in, const int* in_sizes, int n_in,
                              void* d_out, int out_size) {
    const float* x  = (const float*)d_in[0];
    const float* Wx = (const float*)d_in[1];
    const float* bx = (const float*)d_in[2];
    const float* Wh = (const float*)d_in[3];
    const float* bh = (const float*)d_in[4];
    const float* Wp = (const float*)d_in[5];
    const float* bp = (const float*)d_in[6];
    float* out = (float*)d_out;

    cudaFuncSetAttribute(lstm_mma_kernel, cudaFuncAttributeMaxDynamicSharedMemorySize, DYN_SMEM);
    setup_kernel<<<512, 256>>>(x, Wx, Wh);
    lstm_mma_kernel<<<GRID, NT, DYN_SMEM>>>(bx, bh, Wp, bp, out);
}

// round 14
// speedup vs baseline: 1.0557x; 1.0557x over previous
#include <cuda_runtime.h>
#include <cuda_fp16.h>
#include <stdint.h>
#include <math.h>

#define BB 64
#define TT 512
#define II 256
#define HH 1024
#define OO 10
#define KTOT 1280
#define NCOL 4096
#define GRID 128
#define NT 256

#define AROW 2560            // bytes per resident-A row (1280 k * 2B fp16)
#define OFF_B 81920          // per-warp B regions after 80KB resident A
#define WREG 4096            // per-warp chunk region (32 rows * 128B)
#define BUFSTRIDE 32768      // 8 warp-regions per buffer
#define OFF_S (OFF_B + 3 * BUFSTRIDE)   // 180224: reduction scratch
#define DYN_SMEM (OFF_S + 33792)        // 214016

#define SW(o) ((o) ^ (((o) >> 3) & 0x70))

// ---------------- persistent device state ----------------
__device__ __half g_W[NCOL * KTOT];        // [col][k], col = cta*32 + g*8 + hloc
__device__ __half g_x[BB * TT * II];
__device__ __half g_h[2][BB * HH];
__device__ unsigned int g_cnt_grp[16];
__device__ unsigned int g_cnt_top;
__device__ volatile unsigned int g_gen_rep[16 * 32];   // 16 padded release lines

__device__ __forceinline__ uint32_t smem_u32(const void* p) {
    uint32_t a;
    asm("{ .reg .u64 t; cvta.to.shared.u64 t, %1; cvt.u32.u64 %0, t; }" : "=r"(a) : "l"(p));
    return a;
}

#define LDSM4(r, a) \
    asm volatile("ldmatrix.sync.aligned.m8n8.x4.shared.b16 {%0,%1,%2,%3}, [%4];" \
        : "=r"((r)[0]), "=r"((r)[1]), "=r"((r)[2]), "=r"((r)[3]) : "r"(a))

#define MMA(acc, a, b0, b1) \
    asm volatile("mma.sync.aligned.m16n8k16.row.col.f32.f16.f16.f32 " \
        "{%0,%1,%2,%3},{%4,%5,%6,%7},{%8,%9},{%0,%1,%2,%3};" \
        : "+f"((acc)[0]), "+f"((acc)[1]), "+f"((acc)[2]), "+f"((acc)[3]) \
        : "r"((a)[0]), "r"((a)[1]), "r"((a)[2]), "r"((a)[3]), "r"(b0), "r"(b1))

#define CP_ASYNC(dst, src) \
    asm volatile("cp.async.cg.shared.global [%0], [%1], 16;" :: "r"(dst), "l"(src))
#define CP_COMMIT() asm volatile("cp.async.commit_group;" ::: "memory")
#define CP_WAIT0()  asm volatile("cp.async.wait_group 0;" ::: "memory")
#define CP_WAIT1()  asm volatile("cp.async.wait_group 1;" ::: "memory")

__device__ __forceinline__ float fast_tanh(float x) {
    float e = __expf(2.0f * x);
    return 1.0f - 2.0f / (e + 1.0f);
}
__device__ __forceinline__ float fast_sig(float x) {
    return 1.0f / (1.0f + __expf(-x));
}

// ---------------- setup ----------------
__global__ void setup_kernel(const float* __restrict__ x,
                             const float* __restrict__ Wx,
                             const float* __restrict__ Wh)
{
    int gt = blockIdx.x * blockDim.x + threadIdx.x;
    int stride = gridDim.x * blockDim.x;

    for (int i = gt; i < NCOL * KTOT; i += stride) {
        int cf = i / KTOT, k = i - cf * KTOT;
        int cta = cf >> 5, r = cf & 31;
        int g = r >> 3, hj = cta * 8 + (r & 7);
        float w = (k < HH) ? Wh[(g * HH + k) * HH + hj]
                           : Wx[(g * II + (k - HH)) * HH + hj];
        g_W[i] = __float2half(w);
    }
    for (int i = gt; i < BB * TT * II; i += stride)
        g_x[i] = __float2half(x[i]);
    for (int i = gt; i < BB * HH; i += stride)
        g_h[0][i] = __float2half(0.0f);
}

// ---------------- per-warp staging: warp stages the 4KB it will consume ----------------
__device__ __forceinline__ void stage_h_w(const __half* hs, int chunk,
                                          uint32_t region, int nh, int l) {
#pragma unroll
    for (int s = 0; s < 8; s++) {
        int n = s * 4 + (l >> 3);       // local row 0..31
        int kg = l & 7;
        const __half* src = hs + (nh * 32 + n) * HH + chunk * 64 + kg * 8;
        CP_ASYNC(region + SW(n * 128 + kg * 16), src);
    }
    CP_COMMIT();
}

__device__ __forceinline__ void stage_x_w(int tt, int kh,
                                          uint32_t region, int nh, int l) {
#pragma unroll
    for (int s = 0; s < 8; s++) {
        int n = s * 4 + (l >> 3);
        int kg = l & 7;
        const __half* src = g_x + ((nh * 32 + n) * TT + tt) * II + kh * 64 + kg * 8;
        CP_ASYNC(region + SW(n * 128 + kg * 16), src);
    }
    CP_COMMIT();
}

__device__ __forceinline__ void compute_chunk(uint32_t region, int chunk,
                                              uint32_t aB0, uint32_t aB1,
                                              uint32_t bR0,
                                              int la, int lb, int lc,
                                              float acc[2][4][4]) {
#pragma unroll
    for (int ks = 0; ks < 4; ks++) {
        uint32_t ah0[4], ah1[4], bhf[8];
        uint32_t aoff = (uint32_t)(((chunk * 8 + ks * 2 + lc) ^ la) * 16);
        LDSM4(ah0, aB0 + aoff);
        LDSM4(ah1, aB1 + aoff);
        uint32_t boff = (uint32_t)(((ks * 2 + lb) ^ la) * 16);
        LDSM4(bhf,     region + bR0 + boff);
        LDSM4(bhf + 4, region + bR0 + 2048 + boff);
        MMA(acc[0][0], ah0, bhf[0], bhf[1]);
        MMA(acc[0][1], ah0, bhf[2], bhf[3]);
        MMA(acc[0][2], ah0, bhf[4], bhf[5]);
        MMA(acc[0][3], ah0, bhf[6], bhf[7]);
        MMA(acc[1][0], ah1, bhf[0], bhf[1]);
        MMA(acc[1][1], ah1, bhf[2], bhf[3]);
        MMA(acc[1][2], ah1, bhf[4], bhf[5]);
        MMA(acc[1][3], ah1, bhf[6], bhf[7]);
    }
}

// ---------------- persistent HMMA LSTM: warp-self-paced pipeline ----------------
__global__ __launch_bounds__(NT, 1)
void lstm_mma_kernel(const float* __restrict__ bx,
                     const float* __restrict__ bh,
                     const float* __restrict__ Wp,
                     const float* __restrict__ bp,
                     float* __restrict__ out)
{
    extern __shared__ char smem[];
    const uint32_t sb = smem_u32(smem);
    const int tid = threadIdx.x;
    const int w   = tid >> 5;
    const int l   = tid & 31;
    const int cta = blockIdx.x;
    const int col0 = cta * 32;
    const int nh = w & 1;          // batch half: rows nh*32..+31
    const int kh = w >> 1;         // k-split quarter: 0..3

    const int la = l & 7, lb = (l >> 3) & 1, lc = l >> 4;

    const int repidx = (cta >> 3) * 32;
    const unsigned base = g_gen_rep[repidx];   // replay-safe barrier base

    const uint32_t aB0 = sb + (uint32_t)((lb * 8 + la) * AROW);
    const uint32_t aB1 = aB0 + 16 * AROW;
    const uint32_t bR0 = (uint32_t)((lc * 8 + la) * 128);   // local row in warp region
    const uint32_t woff = (uint32_t)(w * WREG);

    // ---- one-time: load resident A (80KB fp16) ----
#pragma unroll 4
    for (int s = 0; s < 20; s++) {
        int idx = tid + s * NT;
        int r = idx / 160, kg = idx - r * 160;
        const __half* src = g_W + (col0 + r) * KTOT + kg * 8;
        uint32_t dst = sb + r * AROW + ((kg ^ (r & 7)) * 16);
        CP_ASYNC(dst, src);
    }
    CP_COMMIT(); CP_WAIT0();
    __syncthreads();

    // epilogue ownership: thread owns b-pair (2l, 2l+1) at hjE = cta*8 + w
    const int hjE = cta * 8 + w;
    const int nh2 = l >> 4;
    const int nf2 = (l >> 2) & 3;
    const int lsrc = w * 4 + (l & 3);
    float biasE[4];
#pragma unroll
    for (int g = 0; g < 4; g++) biasE[g] = bh[g * HH + hjE] + bx[g * HH + hjE];
    float cc2[2] = {0.f, 0.f};

    // prologue: x(0) chunk (16+kh) into buffer 0's warp region
    stage_x_w(0, kh, sb + OFF_B + woff, nh, l);

    for (int t = 0; t < TT; t++) {
        const __half* hs = g_h[t & 1];
        const int bbi = (2 * t) % 3;
        const uint32_t buf0 = sb + OFF_B + (uint32_t)(((bbi + 0) % 3) * BUFSTRIDE) + woff;
        const uint32_t buf1 = sb + OFF_B + (uint32_t)(((bbi + 1) % 3) * BUFSTRIDE) + woff;
        const uint32_t buf2 = sb + OFF_B + (uint32_t)(((bbi + 2) % 3) * BUFSTRIDE) + woff;

        float acc[2][4][4];
#pragma unroll
        for (int mt = 0; mt < 2; mt++)
#pragma unroll
            for (int nf = 0; nf < 4; nf++)
#pragma unroll
                for (int e = 0; e < 4; e++) acc[mt][nf][e] = 0.f;

        // ---- iter0: x chunk (independent of h(t)) ----
        CP_WAIT0();
        __syncwarp();
        compute_chunk(buf0, 16 + kh, aB0, aB1, bR0, la, lb, lc, acc);

        // ---- per-warp barrier wait on group release line ----
        if (l == 0) {
            while ((g_gen_rep[repidx] - base) < (unsigned)t) { }
        }
        __syncwarp();
        __threadfence();

        stage_h_w(hs, 0 + kh, buf1, nh, l);
        stage_h_w(hs, 4 + kh, buf2, nh, l);

        // ---- iter1 ----
        CP_WAIT1();
        __syncwarp();
        stage_h_w(hs, 8 + kh, buf0, nh, l);
        compute_chunk(buf1, 0 + kh, aB0, aB1, bR0, la, lb, lc, acc);

        // ---- iter2 ----
        CP_WAIT1();
        __syncwarp();
        stage_h_w(hs, 12 + kh, buf1, nh, l);
        compute_chunk(buf2, 4 + kh, aB0, aB1, bR0, la, lb, lc, acc);

        // ---- iter3: prefetch x(t+1) ----
        CP_WAIT1();
        __syncwarp();
        const bool more = (t + 1 < TT);
        if (more) stage_x_w(t + 1, kh, buf2, nh, l);
        compute_chunk(buf0, 8 + kh, aB0, aB1, bR0, la, lb, lc, acc);

        // ---- iter4 ----
        if (more) { CP_WAIT1(); } else { CP_WAIT0(); }
        __syncwarp();
        compute_chunk(buf1, 12 + kh, aB0, aB1, bR0, la, lb, lc, acc);

        // ---- all-warp reduction + epilogue (dedicated scratch region) ----
        float* scratch = (float*)(smem + OFF_S);
        {
            float* dst = scratch + (kh * 2 + nh) * 1056;
#pragma unroll
            for (int mt = 0; mt < 2; mt++)
#pragma unroll
                for (int nf = 0; nf < 4; nf++)
#pragma unroll
                    for (int e = 0; e < 4; e++)
                        dst[((mt * 4 + nf) * 4 + e) * 33 + l] = acc[mt][nf][e];
        }
        __syncthreads();

        {
            float z[2][4];
#pragma unroll
            for (int mt = 0; mt < 2; mt++)
#pragma unroll
                for (int e = 0; e < 4; e++) {
                    int row = ((mt * 4 + nf2) * 4 + e) * 33 + lsrc;
                    float s0 = scratch[(0 + nh2) * 1056 + row];
                    float s1 = scratch[(2 + nh2) * 1056 + row];
                    float s2 = scratch[(4 + nh2) * 1056 + row];
                    float s3 = scratch[(6 + nh2) * 1056 + row];
                    z[mt][e] = (s0 + s1) + (s2 + s3);
                }
            __half* hd = g_h[(t + 1) & 1];
#pragma unroll
            for (int par = 0; par < 2; par++) {
                float zg = z[0][par]     + biasE[0];
                float zi = z[0][2 + par] + biasE[1];
                float zf = z[1][par]     + biasE[2];
                float zo = z[1][2 + par] + biasE[3];
                float gg = fast_tanh(zg);
                float ii = fast_sig(zi);
                float ff = fast_sig(zf);
                float oo = fast_sig(zo);
                float cv = gg * ii + cc2[par] * ff;
                cc2[par] = cv;
                float hv = fast_tanh(cv) * oo;
                hd[(2 * l + par) * HH + hjE] = __float2half(hv);
            }
        }
        __syncthreads();   // h stores + scratch reads complete

        // ---- two-level grid barrier ARRIVE + replicated release ----
        if (tid == 0) {
            __threadfence();
            unsigned grp = (unsigned)cta >> 3;
            unsigned o1 = atomicAdd(&g_cnt_grp[grp], 1u);
            if ((o1 & 7u) == 7u) {
                unsigned o2 = atomicAdd(&g_cnt_top, 1u);
                if ((o2 & 15u) == 15u) {
                    __threadfence();
                    unsigned nv = base + (unsigned)(t + 1);
#pragma unroll
                    for (int r = 0; r < 16; r++) g_gen_rep[r * 32] = nv;
                }
            }
        }
    }

    // ---------- final projection + softmax (final h in buffer 0) ----------
    if (blockIdx.x < BB) {
        if (tid == 0) {
            while ((g_gen_rep[repidx] - base) < (unsigned)TT) { }
        }
        __syncthreads();
        __threadfence();

        float* red    = (float*)(smem + OFF_B);
        float* logits = red + NT;
        const int b = blockIdx.x;
        float part[OO];
#pragma unroll
        for (int o = 0; o < OO; o++) part[o] = 0.f;
        for (int k = tid; k < HH; k += NT) {
            unsigned short uh = __ldcg((const unsigned short*)&g_h[0][b * HH + k]);
            float hv = __half2float(__ushort_as_half(uh));
#pragma unroll
            for (int o = 0; o < OO; o++) part[o] += hv * Wp[k * OO + o];
        }
        for (int o = 0; o < OO; o++) {
            red[tid] = part[o];
            __syncthreads();
            for (int s = NT / 2; s > 0; s >>= 1) {
                if (tid < s) red[tid] += red[tid + s];
                __syncthreads();
            }
            if (tid == 0) logits[o] = red[0] + bp[o];
            __syncthreads();
        }
        if (tid == 0) {
            float m = logits[0];
#pragma unroll
            for (int o = 1; o < OO; o++) m = fmaxf(m, logits[o]);
            float s = 0.f, e[OO];
#pragma unroll
            for (int o = 0; o < OO; o++) { e[o] = expf(logits[o] - m); s += e[o]; }
            float inv = 1.0f / s;
#pragma unroll
            for (int o = 0; o < OO; o++) out[b * OO + o] = e[o] * inv;
        }
    }
}

extern "C" void kernel_launch(void* const* d_in, const int* in_sizes, int n_in,
                              void* d_out, int out_size) {
    const float* x  = (const float*)d_in[0];
    const float* Wx = (const float*)d_in[1];
    const float* bx = (const float*)d_in[2];
    const float* Wh = (const float*)d_in[3];
    const float* bh = (const float*)d_in[4];
    const float* Wp = (const float*)d_in[5];
    const float* bp = (const float*)d_in[6];
    float* out = (float*)d_out;

    cudaFuncSetAttribute(lstm_mma_kernel, cudaFuncAttributeMaxDynamicSharedMemorySize, DYN_SMEM);
    setup_kernel<<<512, 256>>>(x, Wx, Wh);
    lstm_mma_kernel<<<GRID, NT, DYN_SMEM>>>(bx, bh, Wp, bp, out);
}

// round 15
// speedup vs baseline: 1.6700x; 1.5819x over previous
#include <cuda_runtime.h>
#include <cuda_fp16.h>
#include <stdint.h>
#include <math.h>

#define BB 64
#define TT 512
#define II 256
#define HH 1024
#define OO 10
#define KTOT 1280
#define NCOL 4096
#define GRID 128
#define NT 256

#define AROW 2560            // bytes per resident-A row (1280 k * 2B fp16)
#define OFF_B 81920          // B buffers after 80KB resident A
#define SLOT  8192           // one 64-k chunk (64 rows * 128B)
#define SLOT4 34816          // one buffer: 4 chunk slots (32KB) + scratch headroom
#define OFF_BASE (OFF_B + 3 * SLOT4)    // 186368: counter bases (64B)
#define DYN_SMEM (OFF_BASE + 64)        // 186432

#define SW(o) ((o) ^ (((o) >> 3) & 0x70))

// ---------------- persistent device state ----------------
__device__ __half g_W[NCOL * KTOT];        // [col][k], col = cta*32 + g*8 + hloc
__device__ __half g_x[BB * TT * II];
__device__ __half g_h[2][BB * HH];
__device__ unsigned int g_rdy[16 * 32];    // per-chunk ready counters, 128B apart

__device__ __forceinline__ uint32_t smem_u32(const void* p) {
    uint32_t a;
    asm("{ .reg .u64 t; cvta.to.shared.u64 t, %1; cvt.u32.u64 %0, t; }" : "=r"(a) : "l"(p));
    return a;
}

#define LDSM4(r, a) \
    asm volatile("ldmatrix.sync.aligned.m8n8.x4.shared.b16 {%0,%1,%2,%3}, [%4];" \
        : "=r"((r)[0]), "=r"((r)[1]), "=r"((r)[2]), "=r"((r)[3]) : "r"(a))

#define MMA(acc, a, b0, b1) \
    asm volatile("mma.sync.aligned.m16n8k16.row.col.f32.f16.f16.f32 " \
        "{%0,%1,%2,%3},{%4,%5,%6,%7},{%8,%9},{%0,%1,%2,%3};" \
        : "+f"((acc)[0]), "+f"((acc)[1]), "+f"((acc)[2]), "+f"((acc)[3]) \
        : "r"((a)[0]), "r"((a)[1]), "r"((a)[2]), "r"((a)[3]), "r"(b0), "r"(b1))

#define CP_ASYNC(dst, src) \
    asm volatile("cp.async.cg.shared.global [%0], [%1], 16;" :: "r"(dst), "l"(src))
#define CP_COMMIT() asm volatile("cp.async.commit_group;" ::: "memory")
#define CP_WAIT0()  asm volatile("cp.async.wait_group 0;" ::: "memory")
#define CP_WAIT1()  asm volatile("cp.async.wait_group 1;" ::: "memory")

__device__ __forceinline__ float fast_tanh(float x) {
    float e = __expf(2.0f * x);
    return 1.0f - 2.0f / (e + 1.0f);
}
__device__ __forceinline__ float fast_sig(float x) {
    return 1.0f / (1.0f + __expf(-x));
}

// ---------------- setup ----------------
__global__ void setup_kernel(const float* __restrict__ x,
                             const float* __restrict__ Wx,
                             const float* __restrict__ Wh)
{
    int gt = blockIdx.x * blockDim.x + threadIdx.x;
    int stride = gridDim.x * blockDim.x;

    for (int i = gt; i < NCOL * KTOT; i += stride) {
        int cf = i / KTOT, k = i - cf * KTOT;
        int cta = cf >> 5, r = cf & 31;
        int g = r >> 3, hj = cta * 8 + (r & 7);
        float w = (k < HH) ? Wh[(g * HH + k) * HH + hj]
                           : Wx[(g * II + (k - HH)) * HH + hj];
        g_W[i] = __float2half(w);
    }
    for (int i = gt; i < BB * TT * II; i += stride)
        g_x[i] = __float2half(x[i]);
    for (int i = gt; i < BB * HH; i += stride)
        g_h[0][i] = __float2half(0.0f);
}

// ---------------- staging helpers (identical to R12) ----------------
__device__ __forceinline__ void stage_h(const __half* hs, int c0,
                                        uint32_t bufbase, int tid) {
#pragma unroll
    for (int s = 0; s < 8; s++) {
        int gi = tid + s * NT;
        int slot = gi >> 9;
        int rem = gi & 511;
        int n = rem >> 3, kg = rem & 7;
        int k = (c0 + slot) * 64 + kg * 8;
        const __half* src = hs + n * HH + k;
        uint32_t dst = bufbase + slot * SLOT + SW(n * 128 + kg * 16);
        CP_ASYNC(dst, src);
    }
}

__device__ __forceinline__ void stage_x(int tt, uint32_t bufbase, int tid) {
#pragma unroll
    for (int s = 0; s < 8; s++) {
        int gi = tid + s * NT;
        int slot = gi >> 9;
        int rem = gi & 511;
        int n = rem >> 3, kg = rem & 7;
        int kx = slot * 64 + kg * 8;
        const __half* src = g_x + (n * TT + tt) * II + kx;
        uint32_t dst = bufbase + slot * SLOT + SW(n * 128 + kg * 16);
        CP_ASYNC(dst, src);
    }
}

__device__ __forceinline__ void compute_chunk(uint32_t slotB, int chunk,
                                              uint32_t aB0, uint32_t aB1,
                                              uint32_t bR0,
                                              int la, int lb, int lc,
                                              float acc[2][4][4]) {
#pragma unroll
    for (int ks = 0; ks < 4; ks++) {
        uint32_t ah0[4], ah1[4], bhf[8];
        uint32_t aoff = (uint32_t)(((chunk * 8 + ks * 2 + lc) ^ la) * 16);
        LDSM4(ah0, aB0 + aoff);
        LDSM4(ah1, aB1 + aoff);
        uint32_t boff = (uint32_t)(((ks * 2 + lb) ^ la) * 16);
        LDSM4(bhf,     slotB + bR0 + boff);
        LDSM4(bhf + 4, slotB + bR0 + 2048 + boff);
        MMA(acc[0][0], ah0, bhf[0], bhf[1]);
        MMA(acc[0][1], ah0, bhf[2], bhf[3]);
        MMA(acc[0][2], ah0, bhf[4], bhf[5]);
        MMA(acc[0][3], ah0, bhf[6], bhf[7]);
        MMA(acc[1][0], ah1, bhf[0], bhf[1]);
        MMA(acc[1][1], ah1, bhf[2], bhf[3]);
        MMA(acc[1][2], ah1, bhf[4], bhf[5]);
        MMA(acc[1][3], ah1, bhf[6], bhf[7]);
    }
}

// ---------------- persistent HMMA LSTM: per-chunk ready-flag sync ----------------
__global__ __launch_bounds__(NT, 1)
void lstm_mma_kernel(const float* __restrict__ bx,
                     const float* __restrict__ bh,
                     const float* __restrict__ Wp,
                     const float* __restrict__ bp,
                     float* __restrict__ out)
{
    extern __shared__ char smem[];
    const uint32_t sb = smem_u32(smem);
    const int tid = threadIdx.x;
    const int w   = tid >> 5;
    const int l   = tid & 31;
    const int cta = blockIdx.x;
    const int col0 = cta * 32;
    const int nh = w & 1;          // batch half: rows nh*32..+31
    const int kh = w >> 1;         // k-split quarter: 0..3

    const int la = l & 7, lb = (l >> 3) & 1, lc = l >> 4;

    const uint32_t aB0 = sb + (uint32_t)((lb * 8 + la) * AROW);
    const uint32_t aB1 = aB0 + 16 * AROW;
    const uint32_t bR0 = (uint32_t)((nh * 32 + lc * 8 + la) * 128);

    // capture replay-safe counter bases (counters are monotonic across replays)
    unsigned* base_s = (unsigned*)(smem + OFF_BASE);
    if (tid < 16) base_s[tid] = *(volatile unsigned*)&g_rdy[tid * 32];

    // ---- one-time: load resident A (80KB fp16) ----
#pragma unroll 4
    for (int s = 0; s < 20; s++) {
        int idx = tid + s * NT;
        int r = idx / 160, kg = idx - r * 160;
        const __half* src = g_W + (col0 + r) * KTOT + kg * 8;
        uint32_t dst = sb + r * AROW + ((kg ^ (r & 7)) * 16);
        CP_ASYNC(dst, src);
    }
    CP_COMMIT(); CP_WAIT0();
    __syncthreads();

    // epilogue ownership: thread owns b-pair (2l, 2l+1) at hjE = cta*8 + w
    const int hjE = cta * 8 + w;
    const int nh2 = l >> 4;
    const int nf2 = (l >> 2) & 3;
    const int lsrc = w * 4 + (l & 3);
    float biasE[4];
#pragma unroll
    for (int g = 0; g < 4; g++) biasE[g] = bh[g * HH + hjE] + bx[g * HH + hjE];
    float cc2[2] = {0.f, 0.f};

    const unsigned mychunk = (unsigned)(cta >> 3);

    // prologue: x(0) into buffer 0
    stage_x(0, sb + OFF_B, tid);
    CP_COMMIT();

    for (int t = 0; t < TT; t++) {
        const __half* hs = g_h[t & 1];
        const unsigned need = 8u * (unsigned)t;
        const int bbi = (2 * t) % 3;
        const uint32_t buf0 = sb + OFF_B + (uint32_t)(((bbi + 0) % 3) * SLOT4);
        const uint32_t buf1 = sb + OFF_B + (uint32_t)(((bbi + 1) % 3) * SLOT4);
        const uint32_t buf2 = sb + OFF_B + (uint32_t)(((bbi + 2) % 3) * SLOT4);

        float acc[2][4][4];
#pragma unroll
        for (int mt = 0; mt < 2; mt++)
#pragma unroll
            for (int nf = 0; nf < 4; nf++)
#pragma unroll
                for (int e = 0; e < 4; e++) acc[mt][nf][e] = 0.f;

        // ---- iter0: compute x chunks (16..19) — no h dependency ----
        CP_WAIT0();
        __syncthreads();
        compute_chunk(buf0 + kh * SLOT, 16 + kh, aB0, aB1, bR0, la, lb, lc, acc);

        // ---- wait chunks 0..7 ready (parallel polls, max-of-8 each) ----
        if (tid < 8) {
            volatile unsigned* p = &g_rdy[tid * 32];
            unsigned b = base_s[tid];
            while ((*p - b) < need) { }
        }
        __syncthreads();
        __threadfence();

        stage_h(hs, 0, buf1, tid); CP_COMMIT();
        stage_h(hs, 4, buf2, tid); CP_COMMIT();

        // ---- iter1: wait chunks 8..11, stage them, compute 0..3 ----
        CP_WAIT1();
        if (tid < 4) {
            volatile unsigned* p = &g_rdy[(8 + tid) * 32];
            unsigned b = base_s[8 + tid];
            while ((*p - b) < need) { }
        }
        __syncthreads();
        stage_h(hs, 8, buf0, tid); CP_COMMIT();
        compute_chunk(buf1 + kh * SLOT, 0 + kh, aB0, aB1, bR0, la, lb, lc, acc);

        // ---- iter2: wait chunks 12..15, stage them, compute 4..7 ----
        CP_WAIT1();
        if (tid < 4) {
            volatile unsigned* p = &g_rdy[(12 + tid) * 32];
            unsigned b = base_s[12 + tid];
            while ((*p - b) < need) { }
        }
        __syncthreads();
        stage_h(hs, 12, buf1, tid); CP_COMMIT();
        compute_chunk(buf2 + kh * SLOT, 4 + kh, aB0, aB1, bR0, la, lb, lc, acc);

        // ---- iter3: prefetch x(t+1), compute 8..11 ----
        CP_WAIT1();
        __syncthreads();
        const bool more = (t + 1 < TT);
        if (more) { stage_x(t + 1, buf2, tid); CP_COMMIT(); }
        compute_chunk(buf0 + kh * SLOT, 8 + kh, aB0, aB1, bR0, la, lb, lc, acc);

        // ---- iter4: compute 12..15 ----
        if (more) { CP_WAIT1(); } else { CP_WAIT0(); }
        __syncthreads();
        compute_chunk(buf1 + kh * SLOT, 12 + kh, aB0, aB1, bR0, la, lb, lc, acc);

        // ---- all-warp reduction + epilogue (scratch in buf0: reads retired) ----
        float* scratch = (float*)(smem + (buf0 - sb));
        {
            float* dst = scratch + (kh * 2 + nh) * 1056;
#pragma unroll
            for (int mt = 0; mt < 2; mt++)
#pragma unroll
                for (int nf = 0; nf < 4; nf++)
#pragma unroll
                    for (int e = 0; e < 4; e++)
                        dst[((mt * 4 + nf) * 4 + e) * 33 + l] = acc[mt][nf][e];
        }
        __syncthreads();

        {
            float z[2][4];
#pragma unroll
            for (int mt = 0; mt < 2; mt++)
#pragma unroll
                for (int e = 0; e < 4; e++) {
                    int row = ((mt * 4 + nf2) * 4 + e) * 33 + lsrc;
                    float s0 = scratch[(0 + nh2) * 1056 + row];
                    float s1 = scratch[(2 + nh2) * 1056 + row];
                    float s2 = scratch[(4 + nh2) * 1056 + row];
                    float s3 = scratch[(6 + nh2) * 1056 + row];
                    z[mt][e] = (s0 + s1) + (s2 + s3);
                }
            __half* hd = g_h[(t + 1) & 1];
#pragma unroll
            for (int par = 0; par < 2; par++) {
                float zg = z[0][par]     + biasE[0];
                float zi = z[0][2 + par] + biasE[1];
                float zf = z[1][par]     + biasE[2];
                float zo = z[1][2 + par] + biasE[3];
                float gg = fast_tanh(zg);
                float ii = fast_sig(zi);
                float ff = fast_sig(zf);
                float oo = fast_sig(zo);
                float cv = gg * ii + cc2[par] * ff;
                cc2[par] = cv;
                float hv = fast_tanh(cv) * oo;
                hd[(2 * l + par) * HH + hjE] = __float2half(hv);
            }
        }
        __threadfence();   // make this thread's h stores globally visible
        __syncthreads();   // all threads' stores fenced before arrive

        // ---- per-chunk arrive: 8-way contended counter ----
        if (tid == 0)
            atomicAdd(&g_rdy[mychunk * 32], 1u);
    }

    // ---------- final projection + softmax (final h in buffer 0) ----------
    if (blockIdx.x < BB) {
        if (tid < 16) {
            volatile unsigned* p = &g_rdy[tid * 32];
            unsigned b = base_s[tid];
            while ((*p - b) < 8u * (unsigned)TT) { }
        }
        __syncthreads();
        __threadfence();

        float* red    = (float*)(smem + OFF_B);
        float* logits = red + NT;
        const int b = blockIdx.x;
        float part[OO];
#pragma unroll
        for (int o = 0; o < OO; o++) part[o] = 0.f;
        for (int k = tid; k < HH; k += NT) {
            unsigned short uh = __ldcg((const unsigned short*)&g_h[0][b * HH + k]);
            float hv = __half2float(__ushort_as_half(uh));
#pragma unroll
            for (int o = 0; o < OO; o++) part[o] += hv * Wp[k * OO + o];
        }
        for (int o = 0; o < OO; o++) {
            red[tid] = part[o];
            __syncthreads();
            for (int s = NT / 2; s > 0; s >>= 1) {
                if (tid < s) red[tid] += red[tid + s];
                __syncthreads();
            }
            if (tid == 0) logits[o] = red[0] + bp[o];
            __syncthreads();
        }
        if (tid == 0) {
            float m = logits[0];
#pragma unroll
            for (int o = 1; o < OO; o++) m = fmaxf(m, logits[o]);
            float s = 0.f, e[OO];
#pragma unroll
            for (int o = 0; o < OO; o++) { e[o] = expf(logits[o] - m); s += e[o]; }
            float inv = 1.0f / s;
#pragma unroll
            for (int o = 0; o < OO; o++) out[b * OO + o] = e[o] * inv;
        }
    }
}

extern "C" void kernel_launch(void* const* d_in, const int* in_sizes, int n_in,
                              void* d_out, int out_size) {
    const float* x  = (const float*)d_in[0];
    const float* Wx = (const float*)d_in[1];
    const float* bx = (const float*)d_in[2];
    const float* Wh = (const float*)d_in[3];
    const float* bh = (const float*)d_in[4];
    const float* Wp = (const float*)d_in[5];
    const float* bp = (const float*)d_in[6];
    float* out = (float*)d_out;

    cudaFuncSetAttribute(lstm_mma_kernel, cudaFuncAttributeMaxDynamicSharedMemorySize, DYN_SMEM);
    setup_kernel<<<512, 256>>>(x, Wx, Wh);
    lstm_mma_kernel<<<GRID, NT, DYN_SMEM>>>(bx, bh, Wp, bp, out);
}